// round 3
// baseline (speedup 1.0000x reference)
#include <cuda_runtime.h>

#define TT    2048
#define BB    32
#define FEATD 512
#define HIDD  512
#define NCOL4 2048           // 4*HID
#define NCTA  128            // persistent CTAs (1 per SM, <=148 -> co-resident)
#define NH    4              // hidden units per CTA
#define NC    16             // gate columns per CTA (4 hidden x 4 gates)
#define KTOT  1024           // fused K = FEAT + HID
#define ZS    1028           // padded floats per b-row of z
#define NTHR  256
#define ROWSZ (BB*HIDD)      // 16384 floats per timestep of h

// h history buffers: row r holds h after step r-1; row 0 stays zero forever
// (never written), giving h_{-1}=0 deterministically across graph replays.
__device__ __align__(256) float g_hA[(TT+1)*ROWSZ];
__device__ __align__(256) float g_hB[(TT+1)*ROWSZ];
__device__ unsigned int g_count = 0;
__device__ unsigned int g_gen   = 0;

// Self-resetting grid barrier. g_gen is monotonic (works across replays),
// g_count returns to 0 at every barrier, so launch-start state is clean.
__device__ __forceinline__ void grid_barrier() {
    __threadfence();
    __syncthreads();
    if (threadIdx.x == 0) {
        volatile unsigned int* vgen = &g_gen;
        unsigned int gen = *vgen;
        if (atomicAdd(&g_count, 1u) == NCTA - 1u) {
            atomicExch(&g_count, 0u);
            __threadfence();
            atomicAdd(&g_gen, 1u);
        } else {
            while (*vgen == gen) {}
        }
    }
    __syncthreads();
}

// Robust length load: JAX silently downcasts int64->int32 unless x64 mode is
// on, so the buffer may hold either. All lengths are in [0, 2048); if the data
// is int64 (little-endian), every odd 32-bit word is 0. If it's int32, the odd
// words are real lengths, all-zero with probability (1/2048)^16 ~ 0.
__device__ __forceinline__ int load_length(const void* lp, int b) {
    const int* L = (const int*)lp;
    bool is64 = true;
    #pragma unroll
    for (int w = 1; w < 32; w += 2) is64 &= (L[w] == 0);
    return is64 ? (int)((const long long*)lp)[b] : L[b];
}

__global__ void __launch_bounds__(NTHR, 1)
lstm_persistent(const float* __restrict__ x,
                const void* __restrict__ length,
                const float* __restrict__ Wih0, const float* __restrict__ Whh0,
                const float* __restrict__ b0v,
                const float* __restrict__ Wih1, const float* __restrict__ Whh1,
                const float* __restrict__ b1v)
{
    extern __shared__ float smem[];
    float* z_s     = smem;                 // [b][k] : 32 x 1028
    float* W_s     = z_s + BB*ZS;          // 16384 floats, transposed + k-interleaved
    float* gates_s = W_s + KTOT*NC;        // 32 x 17 (padded)

    const int tid = threadIdx.x;
    const int hbase = blockIdx.x * NH;

    // compute-phase mapping: lane -> (c, bh); warp -> (kh, bg)
    const int c   = tid & 15;              // gate column within CTA (c = hh*4 + g)
    const int bh  = (tid >> 4) & 1;
    const int bg  = (tid >> 5) & 3;
    const int kh  = tid >> 7;              // k-half (0: k<512, 1: k>=512)
    const int b0i = bg*8 + bh*4;           // first of 4 batch rows for this thread

    // elementwise-phase mapping (tid < 128): thread owns state (b, hh)
    const int eb  = tid & 31;
    const int ehh = tid >> 5;
    int lb = 0;
    if (tid < 128) lb = load_length(length, eb);

    for (int layer = 0; layer < 2; ++layer) {
        const float* Wih  = layer ? Wih1 : Wih0;
        const float* Whh  = layer ? Whh1 : Whh0;
        const float* bias = layer ? b1v  : b0v;
        const float* xbase = layer ? (g_hA + ROWSZ) : x;   // layer1 input at t = g_hA row t+1
        float* hbuf = layer ? g_hB : g_hA;

        // Stage weights: W_s[(k>>2)*64 + c*4 + (k&3)] = W[k][col(c)]
        for (int i = tid; i < KTOT*NC; i += NTHR) {
            int k  = i >> 4;
            int cc = i & 15;
            int col = ((cc & 3) << 9) + hbase + (cc >> 2);   // gate*512 + hidden
            float w = (k < FEATD) ? Wih[(size_t)k*NCOL4 + col]
                                  : Whh[(size_t)(k-FEATD)*NCOL4 + col];
            W_s[((k >> 2) << 6) + (cc << 2) + (k & 3)] = w;
        }
        float bv = bias[((c & 3) << 9) + hbase + (c >> 2)];

        float creg = 0.f;    // cell state, owned by thread (tid<128): (eb, ehh)
        float hreg = 0.f;    // previous h for frozen lanes
        __syncthreads();

        for (int t = 0; t < TT; ++t) {
            // ---- stage z = [x_t ; h_prev] as [b][k], coalesced, conflict-free ----
            const float4* xs4 = (const float4*)(xbase + (size_t)t*ROWSZ);
            const float4* hs4 = (const float4*)(hbuf  + (size_t)t*ROWSZ);
            for (int i = tid; i < ROWSZ/4; i += NTHR) {
                int b  = i >> 7;
                int k4 = i & 127;
                float4 vx = __ldcg(xs4 + i);
                *(float4*)(z_s + b*ZS + (k4 << 2)) = vx;
                float4 vh = __ldcg(hs4 + i);
                *(float4*)(z_s + b*ZS + FEATD + (k4 << 2)) = vh;
            }
            __syncthreads();

            // ---- GEMM: acc[c][b0i..b0i+3] over this thread's k-half ----
            float a0 = 0.f, a1 = 0.f, a2 = 0.f, a3 = 0.f;
            {
                const float* wp = W_s + kh*8192 + (c << 2);
                const float* zp = z_s + b0i*ZS + kh*512;
                #pragma unroll 4
                for (int k4 = 0; k4 < 128; ++k4) {
                    float4 w  = *(const float4*)(wp + (k4 << 6));
                    float4 z0 = *(const float4*)(zp + (k4 << 2));
                    float4 z1 = *(const float4*)(zp + ZS   + (k4 << 2));
                    float4 z2 = *(const float4*)(zp + 2*ZS + (k4 << 2));
                    float4 z3 = *(const float4*)(zp + 3*ZS + (k4 << 2));
                    a0 += z0.x*w.x; a0 += z0.y*w.y; a0 += z0.z*w.z; a0 += z0.w*w.w;
                    a1 += z1.x*w.x; a1 += z1.y*w.y; a1 += z1.z*w.z; a1 += z1.w*w.w;
                    a2 += z2.x*w.x; a2 += z2.y*w.y; a2 += z2.z*w.z; a2 += z2.w*w.w;
                    a3 += z3.x*w.x; a3 += z3.y*w.y; a3 += z3.z*w.z; a3 += z3.w*w.w;
                }
            }
            if (kh == 1) {
                gates_s[(b0i+0)*17 + c] = a0;
                gates_s[(b0i+1)*17 + c] = a1;
                gates_s[(b0i+2)*17 + c] = a2;
                gates_s[(b0i+3)*17 + c] = a3;
            }
            __syncthreads();
            if (kh == 0) {
                gates_s[(b0i+0)*17 + c] += a0 + bv;
                gates_s[(b0i+1)*17 + c] += a1 + bv;
                gates_s[(b0i+2)*17 + c] += a2 + bv;
                gates_s[(b0i+3)*17 + c] += a3 + bv;
            }
            __syncthreads();

            // ---- LSTM elementwise: one thread per (b, hidden) state ----
            if (tid < 128) {
                float fg = gates_s[eb*17 + ehh*4 + 0];
                float ig = gates_s[eb*17 + ehh*4 + 1];
                float og = gates_s[eb*17 + ehh*4 + 2];
                float gg = gates_s[eb*17 + ehh*4 + 3];
                float cn, hn;
                if (t < lb) {
                    float sf = 1.f/(1.f + expf(-fg));
                    float si = 1.f/(1.f + expf(-ig));
                    float so = 1.f/(1.f + expf(-og));
                    cn = sf*creg + si*tanhf(gg);
                    hn = so*tanhf(cn);
                } else {
                    cn = creg;
                    hn = hreg;
                }
                creg = cn;
                hreg = hn;
                hbuf[(size_t)(t+1)*ROWSZ + eb*HIDD + hbase + ehh] = hn;
            }
            grid_barrier();   // h row t+1 visible to all CTAs before step t+1
        }
    }
}

// out[r][a] = h1[r] . Wfc[:,a] + bfc[a],  r = t*B + b, h1 row = g_hB row r+32
__global__ void __launch_bounds__(256)
fc_kernel(const float* __restrict__ Wfc, const float* __restrict__ bfc,
          float* __restrict__ out)
{
    __shared__ float w_s[128*64];
    __shared__ float h_s[32*128];
    const int tid = threadIdx.x;
    const int rbase = blockIdx.x * 32;
    const int a  = tid & 63;
    const int r4 = tid >> 6;        // 0..3

    float acc[8];
    float bvv = bfc[a];
    #pragma unroll
    for (int j = 0; j < 8; ++j) acc[j] = bvv;

    for (int kc = 0; kc < 512; kc += 128) {
        __syncthreads();
        for (int i = tid; i < 128*64/4; i += 256)
            ((float4*)w_s)[i] = ((const float4*)(Wfc + (size_t)kc*64))[i];
        for (int i = tid; i < 32*128/4; i += 256) {
            int r  = i >> 5;
            int k4 = i & 31;
            ((float4*)(h_s + r*128))[k4] =
                *(const float4*)(g_hB + (size_t)(rbase + r + BB)*HIDD + kc + (k4 << 2));
        }
        __syncthreads();
        #pragma unroll 4
        for (int k = 0; k < 128; ++k) {
            float w = w_s[(k << 6) + a];
            #pragma unroll
            for (int j = 0; j < 8; ++j)
                acc[j] += h_s[(r4 + 4*j)*128 + k] * w;
        }
    }
    #pragma unroll
    for (int j = 0; j < 8; ++j)
        out[(size_t)(rbase + r4 + 4*j)*64 + a] = acc[j];
}

extern "C" void kernel_launch(void* const* d_in, const int* in_sizes, int n_in,
                              void* d_out, int out_size)
{
    const float* x      = (const float*)d_in[0];
    const void*  length = (const void*)d_in[1];
    const float* Wih0   = (const float*)d_in[2];
    const float* Whh0   = (const float*)d_in[3];
    const float* b0v    = (const float*)d_in[4];
    const float* Wih1   = (const float*)d_in[5];
    const float* Whh1   = (const float*)d_in[6];
    const float* b1v    = (const float*)d_in[7];
    const float* Wfc    = (const float*)d_in[8];
    const float* bfc    = (const float*)d_in[9];
    float* out = (float*)d_out;

    const int smem_bytes = (BB*ZS + KTOT*NC + 32*17) * (int)sizeof(float); // ~199 KB
    cudaFuncSetAttribute(lstm_persistent,
                         cudaFuncAttributeMaxDynamicSharedMemorySize, smem_bytes);

    lstm_persistent<<<NCTA, NTHR, smem_bytes>>>(x, length, Wih0, Whh0, b0v,
                                                Wih1, Whh1, b1v);
    fc_kernel<<<(TT*BB)/32, 256>>>(Wfc, bfc, out);
}